// round 1
// baseline (speedup 1.0000x reference)
#include <cuda_runtime.h>

// Problem constants
static constexpr int  Bc  = 2;
static constexpr int  Tc  = 2048;
static constexpr int  Dc  = 1024;
static constexpr int  Hc  = 16;
static constexpr int  DKc = 64;
static constexpr long long OUT_ELEMS = (long long)Bc * Tc * Dc;          // 4194304
static constexpr long long W_ELEMS   = (long long)Bc * Hc * Tc * Tc;     // 134217728

// Scratch (allocation-free rule: __device__ globals)
__device__ float g_q[Bc * Tc * Dc];
__device__ float g_k[Bc * Tc * Dc];
__device__ float g_v[Bc * Tc * Dc];
__device__ float g_attn[Bc * Tc * Dc];
__device__ float g_weights[(size_t)Bc * Hc * Tc * Tc];  // fallback if harness only wants `out`

// ---------------------------------------------------------------------------
// C[M,N] = alpha * A[M,K] * B[N,K]^T   (both operands K-major / row-major)
// Tiles: 128x128x16, 256 threads, 8x8 per thread.
// Batched over blockIdx.z with split (batch, head) strides: off = b*s_b + h*s_h
// ---------------------------------------------------------------------------
__global__ __launch_bounds__(256) void gemm_nt_kernel(
    const float* __restrict__ A, const float* __restrict__ Bm, float* __restrict__ C,
    int K, int lda, int ldb, int ldc, int nh,
    long long sAb, long long sAh, long long sBb, long long sBh,
    long long sCb, long long sCh, float alpha)
{
    constexpr int BM = 128, BN = 128, BK = 16;
    __shared__ float As[BK][BM + 4];
    __shared__ float Bs[BK][BN + 4];

    const int bz = blockIdx.z / nh;
    const int hz = blockIdx.z - bz * nh;
    const float* Ab = A  + bz * sAb + hz * sAh + (long long)blockIdx.y * BM * lda;
    const float* Bb = Bm + bz * sBb + hz * sBh + (long long)blockIdx.x * BN * ldb;
    float*       Cb = C  + bz * sCb + hz * sCh + (long long)blockIdx.y * BM * ldc
                        + (long long)blockIdx.x * BN;

    const int t   = threadIdx.x;
    const int tr  = t >> 4;           // 0..15
    const int tc  = t & 15;           // 0..15
    const int arow = t >> 2;          // 0..63
    const int ac4  = (t & 3) * 4;     // 0,4,8,12

    float acc[8][8];
#pragma unroll
    for (int i = 0; i < 8; i++)
#pragma unroll
        for (int j = 0; j < 8; j++) acc[i][j] = 0.f;

    for (int k0 = 0; k0 < K; k0 += BK) {
#pragma unroll
        for (int i = 0; i < 2; i++) {
            const int row = arow + i * 64;
            float4 va = *(const float4*)(Ab + (long long)row * lda + (k0 + ac4));
            As[ac4 + 0][row] = va.x; As[ac4 + 1][row] = va.y;
            As[ac4 + 2][row] = va.z; As[ac4 + 3][row] = va.w;
            float4 vb = *(const float4*)(Bb + (long long)row * ldb + (k0 + ac4));
            Bs[ac4 + 0][row] = vb.x; Bs[ac4 + 1][row] = vb.y;
            Bs[ac4 + 2][row] = vb.z; Bs[ac4 + 3][row] = vb.w;
        }
        __syncthreads();
#pragma unroll
        for (int k = 0; k < BK; k++) {
            float a[8], b[8];
            *(float4*)(a)     = *(const float4*)&As[k][tr * 8];
            *(float4*)(a + 4) = *(const float4*)&As[k][tr * 8 + 4];
            *(float4*)(b)     = *(const float4*)&Bs[k][tc * 8];
            *(float4*)(b + 4) = *(const float4*)&Bs[k][tc * 8 + 4];
#pragma unroll
            for (int i = 0; i < 8; i++)
#pragma unroll
                for (int j = 0; j < 8; j++)
                    acc[i][j] = fmaf(a[i], b[j], acc[i][j]);
        }
        __syncthreads();
    }

#pragma unroll
    for (int i = 0; i < 8; i++) {
        float* cp = Cb + (long long)(tr * 8 + i) * ldc + tc * 8;
        *(float4*)(cp)     = make_float4(acc[i][0] * alpha, acc[i][1] * alpha,
                                         acc[i][2] * alpha, acc[i][3] * alpha);
        *(float4*)(cp + 4) = make_float4(acc[i][4] * alpha, acc[i][5] * alpha,
                                         acc[i][6] * alpha, acc[i][7] * alpha);
    }
}

// ---------------------------------------------------------------------------
// C[M,N] = A[M,K] * B[K,N]   (PV: weights[2048,2048] @ v[2048,64])
// Tiles: 128x64x32, 256 threads, 8x4 per thread. Grid.x == 1 (N==64).
// ---------------------------------------------------------------------------
__global__ __launch_bounds__(256) void gemm_nn_kernel(
    const float* __restrict__ A, const float* __restrict__ Bm, float* __restrict__ C,
    int K, int lda, int ldb, int ldc, int nh,
    long long sAb, long long sAh, long long sBb, long long sBh,
    long long sCb, long long sCh)
{
    constexpr int BM = 128, BK = 32;
    __shared__ float As[BK][BM + 4];
    __shared__ float Bs[BK][64];

    const int bz = blockIdx.z / nh;
    const int hz = blockIdx.z - bz * nh;
    const float* Ab = A  + bz * sAb + hz * sAh + (long long)blockIdx.y * BM * lda;
    const float* Bb = Bm + bz * sBb + hz * sBh;
    float*       Cb = C  + bz * sCb + hz * sCh + (long long)blockIdx.y * BM * ldc;

    const int t  = threadIdx.x;
    const int tr = t >> 4, tc = t & 15;

    float acc[8][4];
#pragma unroll
    for (int i = 0; i < 8; i++)
#pragma unroll
        for (int j = 0; j < 4; j++) acc[i][j] = 0.f;

    for (int k0 = 0; k0 < K; k0 += BK) {
#pragma unroll
        for (int i = 0; i < 4; i++) {
            const int idx = i * 256 + t;
            const int row = idx >> 3;
            const int kq  = (idx & 7) * 4;
            float4 va = *(const float4*)(Ab + (long long)row * lda + (k0 + kq));
            As[kq + 0][row] = va.x; As[kq + 1][row] = va.y;
            As[kq + 2][row] = va.z; As[kq + 3][row] = va.w;
        }
#pragma unroll
        for (int i = 0; i < 2; i++) {
            const int idx  = i * 256 + t;
            const int krow = idx >> 4;
            const int nq   = (idx & 15) * 4;
            *(float4*)&Bs[krow][nq] =
                *(const float4*)(Bb + (long long)(k0 + krow) * ldb + nq);
        }
        __syncthreads();
#pragma unroll
        for (int k = 0; k < BK; k++) {
            float a[8];
            *(float4*)(a)     = *(const float4*)&As[k][tr * 8];
            *(float4*)(a + 4) = *(const float4*)&As[k][tr * 8 + 4];
            float4 b4 = *(const float4*)&Bs[k][tc * 4];
#pragma unroll
            for (int i = 0; i < 8; i++) {
                acc[i][0] = fmaf(a[i], b4.x, acc[i][0]);
                acc[i][1] = fmaf(a[i], b4.y, acc[i][1]);
                acc[i][2] = fmaf(a[i], b4.z, acc[i][2]);
                acc[i][3] = fmaf(a[i], b4.w, acc[i][3]);
            }
        }
        __syncthreads();
    }

#pragma unroll
    for (int i = 0; i < 8; i++) {
        *(float4*)(Cb + (long long)(tr * 8 + i) * ldc + tc * 4) =
            make_float4(acc[i][0], acc[i][1], acc[i][2], acc[i][3]);
    }
}

// ---------------------------------------------------------------------------
// Row softmax over last axis (row length 2048), one block (256 threads) per row.
// In-place on the weights buffer.
// ---------------------------------------------------------------------------
__global__ __launch_bounds__(256) void softmax_kernel(float* __restrict__ Wt)
{
    float* p = Wt + (long long)blockIdx.x * 2048;
    const int t = threadIdx.x;
    float4 x0 = ((const float4*)p)[t];
    float4 x1 = ((const float4*)p)[t + 256];

    float m = fmaxf(fmaxf(fmaxf(x0.x, x0.y), fmaxf(x0.z, x0.w)),
                    fmaxf(fmaxf(x1.x, x1.y), fmaxf(x1.z, x1.w)));
#pragma unroll
    for (int o = 16; o; o >>= 1) m = fmaxf(m, __shfl_xor_sync(0xffffffffu, m, o));

    __shared__ float redm[8], reds[8];
    if ((t & 31) == 0) redm[t >> 5] = m;
    __syncthreads();
    m = redm[0];
#pragma unroll
    for (int i = 1; i < 8; i++) m = fmaxf(m, redm[i]);

    x0.x = __expf(x0.x - m); x0.y = __expf(x0.y - m);
    x0.z = __expf(x0.z - m); x0.w = __expf(x0.w - m);
    x1.x = __expf(x1.x - m); x1.y = __expf(x1.y - m);
    x1.z = __expf(x1.z - m); x1.w = __expf(x1.w - m);

    float s = x0.x + x0.y + x0.z + x0.w + x1.x + x1.y + x1.z + x1.w;
#pragma unroll
    for (int o = 16; o; o >>= 1) s += __shfl_xor_sync(0xffffffffu, s, o);
    if ((t & 31) == 0) reds[t >> 5] = s;
    __syncthreads();
    s = reds[0] + reds[1] + reds[2] + reds[3] + reds[4] + reds[5] + reds[6] + reds[7];

    const float inv = 1.0f / s;
    x0.x *= inv; x0.y *= inv; x0.z *= inv; x0.w *= inv;
    x1.x *= inv; x1.y *= inv; x1.z *= inv; x1.w *= inv;
    ((float4*)p)[t]       = x0;
    ((float4*)p)[t + 256] = x1;
}

// ---------------------------------------------------------------------------
extern "C" void kernel_launch(void* const* d_in, const int* /*in_sizes*/, int /*n_in*/,
                              void* d_out, int out_size)
{
    const float* query = (const float*)d_in[0];
    const float* key_i = (const float*)d_in[1];
    const float* value = (const float*)d_in[2];
    const float* Wq    = (const float*)d_in[3];
    const float* Wk    = (const float*)d_in[4];
    const float* Wv    = (const float*)d_in[5];
    const float* Wo    = (const float*)d_in[6];
    float* out = (float*)d_out;

    float *q, *k, *v, *attn, *wbuf;
    cudaGetSymbolAddress((void**)&q,    g_q);
    cudaGetSymbolAddress((void**)&k,    g_k);
    cudaGetSymbolAddress((void**)&v,    g_v);
    cudaGetSymbolAddress((void**)&attn, g_attn);
    if ((long long)out_size >= OUT_ELEMS + W_ELEMS) {
        wbuf = out + OUT_ELEMS;                 // tuple-concat output: [out | weights]
    } else {
        cudaGetSymbolAddress((void**)&wbuf, g_weights);
    }

    const long long TD = (long long)Tc * Dc;
    const long long TT = (long long)Tc * Tc;

    // 1) Projections: y = x @ W^T   (M=B*T=4096, N=D=1024, K=D=1024)
    dim3 gp(Dc / 128, (Bc * Tc) / 128, 1);
    gemm_nt_kernel<<<gp, 256>>>(query, Wq, q, Dc, Dc, Dc, Dc, 1, 0, 0, 0, 0, 0, 0, 1.f);
    gemm_nt_kernel<<<gp, 256>>>(key_i, Wk, k, Dc, Dc, Dc, Dc, 1, 0, 0, 0, 0, 0, 0, 1.f);
    gemm_nt_kernel<<<gp, 256>>>(value, Wv, v, Dc, Dc, Dc, Dc, 1, 0, 0, 0, 0, 0, 0, 1.f);

    // 2) Scores = (q_h @ k_h^T) / sqrt(DK)  per (b,h); weights layout [B,H,T,T]
    dim3 gs(Tc / 128, Tc / 128, Bc * Hc);
    gemm_nt_kernel<<<gs, 256>>>(q, k, wbuf, DKc, Dc, Dc, Tc, Hc,
                                TD, DKc, TD, DKc,
                                (long long)Hc * TT, TT, 0.125f);

    // 3) Row softmax over 2048-length rows (B*H*T rows)
    softmax_kernel<<<Bc * Hc * Tc, 256>>>(wbuf);

    // 4) attn = weights @ v  per (b,h) -> packed back into [B,T,D]
    dim3 gv(1, Tc / 128, Bc * Hc);
    gemm_nn_kernel<<<gv, 256>>>(wbuf, v, attn, Tc, Tc, Dc, Dc, Hc,
                                (long long)Hc * TT, TT,
                                TD, DKc, TD, DKc);

    // 5) out = attn @ Wo^T
    gemm_nt_kernel<<<gp, 256>>>(attn, Wo, out, Dc, Dc, Dc, Dc, 1, 0, 0, 0, 0, 0, 0, 1.f);
}

// round 2
// speedup vs baseline: 2.5388x; 2.5388x over previous
#include <cuda_runtime.h>
#include <cstdint>

// Problem constants
static constexpr int  Bc  = 2;
static constexpr int  Tc  = 2048;
static constexpr int  Dc  = 1024;
static constexpr int  Hc  = 16;
static constexpr int  DKc = 64;
static constexpr long long OUT_ELEMS = (long long)Bc * Tc * Dc;          // 4194304
static constexpr long long W_ELEMS   = (long long)Bc * Hc * Tc * Tc;     // 134217728

// Scratch (allocation-free rule: __device__ globals)
__device__ float g_q[Bc * Tc * Dc];
__device__ float g_k[Bc * Tc * Dc];
__device__ float g_v[Bc * Tc * Dc];
__device__ float g_attn[Bc * Tc * Dc];
__device__ float g_weights[(size_t)Bc * Hc * Tc * Tc];  // fallback if out_size has no weights

// ---------------------------------------------------------------------------
// TF32 helpers
// ---------------------------------------------------------------------------
__device__ __forceinline__ uint32_t f2tf(float x) {
    uint32_t r;
    asm("cvt.rna.tf32.f32 %0, %1;" : "=r"(r) : "f"(x));
    return r;
}

__device__ __forceinline__ void mma_tf32(float* c, const uint32_t* a, const uint32_t* b) {
    asm volatile(
        "mma.sync.aligned.m16n8k8.row.col.f32.tf32.tf32.f32 "
        "{%0,%1,%2,%3}, {%4,%5,%6,%7}, {%8,%9}, {%0,%1,%2,%3};\n"
        : "+f"(c[0]), "+f"(c[1]), "+f"(c[2]), "+f"(c[3])
        : "r"(a[0]), "r"(a[1]), "r"(a[2]), "r"(a[3]), "r"(b[0]), "r"(b[1]));
}

// ---------------------------------------------------------------------------
// NT: C[M,N] = alpha * A[M,K] * B[N,K]^T, both row-major (K contiguous).
// Tiles: 128x128x32, 256 threads (8 warps = 2Mx4N, warp tile 64x32).
// Batched over blockIdx.z: off = b*s_b + h*s_h.
// ---------------------------------------------------------------------------
__global__ __launch_bounds__(256) void gemm_nt_tc(
    const float* __restrict__ A, const float* __restrict__ Bm, float* __restrict__ C,
    int K, int lda, int ldb, int ldc, int nh,
    long long sAb, long long sAh, long long sBb, long long sBh,
    long long sCb, long long sCh, float alpha)
{
    constexpr int BM = 128, BN = 128, BK = 32;
    __shared__ float As[BM][BK + 4];   // [m][k], pad 4 -> conflict-free frag reads
    __shared__ float Bs[BN][BK + 4];   // [n][k]

    const int bz = blockIdx.z / nh;
    const int hz = blockIdx.z - bz * nh;
    const float* Ab = A  + bz * sAb + hz * sAh + (long long)blockIdx.y * BM * lda;
    const float* Bb = Bm + bz * sBb + hz * sBh + (long long)blockIdx.x * BN * ldb;
    float*       Cb = C  + bz * sCb + hz * sCh + (long long)blockIdx.y * BM * ldc
                        + (long long)blockIdx.x * BN;

    const int t    = threadIdx.x;
    const int warp = t >> 5, lane = t & 31;
    const int g = lane >> 2, tg = lane & 3;       // groupID, thread-in-group
    const int m_base = (warp & 1) * 64;           // 2 warps along M
    const int n_base = (warp >> 1) * 32;          // 4 warps along N

    float c[4][4][4];
#pragma unroll
    for (int i = 0; i < 4; i++)
#pragma unroll
        for (int j = 0; j < 4; j++)
#pragma unroll
            for (int r = 0; r < 4; r++) c[i][j][r] = 0.f;

    for (int k0 = 0; k0 < K; k0 += BK) {
#pragma unroll
        for (int i = 0; i < 4; i++) {
            const int idx = i * 256 + t;
            const int r   = idx >> 3;
            const int c4  = (idx & 7) * 4;
            *(float4*)&As[r][c4] = *(const float4*)(Ab + (long long)r * lda + k0 + c4);
            *(float4*)&Bs[r][c4] = *(const float4*)(Bb + (long long)r * ldb + k0 + c4);
        }
        __syncthreads();

#pragma unroll
        for (int kk = 0; kk < BK; kk += 8) {
            uint32_t af[4][4], bf[4][2];
#pragma unroll
            for (int mi = 0; mi < 4; mi++) {
                const int m = m_base + mi * 16;
                af[mi][0] = f2tf(As[m + g][kk + tg]);
                af[mi][1] = f2tf(As[m + 8 + g][kk + tg]);
                af[mi][2] = f2tf(As[m + g][kk + 4 + tg]);
                af[mi][3] = f2tf(As[m + 8 + g][kk + 4 + tg]);
            }
#pragma unroll
            for (int ni = 0; ni < 4; ni++) {
                const int n = n_base + ni * 8;
                bf[ni][0] = f2tf(Bs[n + g][kk + tg]);
                bf[ni][1] = f2tf(Bs[n + g][kk + 4 + tg]);
            }
#pragma unroll
            for (int mi = 0; mi < 4; mi++)
#pragma unroll
                for (int ni = 0; ni < 4; ni++)
                    mma_tf32(c[mi][ni], af[mi], bf[ni]);
        }
        __syncthreads();
    }

#pragma unroll
    for (int mi = 0; mi < 4; mi++) {
#pragma unroll
        for (int ni = 0; ni < 4; ni++) {
            const int row = m_base + mi * 16 + g;
            const int col = n_base + ni * 8 + tg * 2;
            *(float2*)(Cb + (long long)row * ldc + col) =
                make_float2(c[mi][ni][0] * alpha, c[mi][ni][1] * alpha);
            *(float2*)(Cb + (long long)(row + 8) * ldc + col) =
                make_float2(c[mi][ni][2] * alpha, c[mi][ni][3] * alpha);
        }
    }
}

// ---------------------------------------------------------------------------
// NN: C[M,N] = A[M,K] * B[K,N]  (PV: weights[2048,2048] @ v[2048,64])
// Tiles: 128x64x32, 256 threads (8 warps = 4Mx2N, warp tile 32x32).
// ---------------------------------------------------------------------------
__global__ __launch_bounds__(256) void gemm_nn_tc(
    const float* __restrict__ A, const float* __restrict__ Bm, float* __restrict__ C,
    int K, int lda, int ldb, int ldc, int nh,
    long long sAb, long long sAh, long long sBb, long long sBh,
    long long sCb, long long sCh)
{
    constexpr int BM = 128, BN = 64, BK = 32;
    __shared__ float As[BM][BK + 4];   // [m][k]
    __shared__ float Bs[BK][BN + 8];   // [k][n], pad 8 -> conflict-free frag reads

    const int bz = blockIdx.z / nh;
    const int hz = blockIdx.z - bz * nh;
    const float* Ab = A  + bz * sAb + hz * sAh + (long long)blockIdx.y * BM * lda;
    const float* Bb = Bm + bz * sBb + hz * sBh;
    float*       Cb = C  + bz * sCb + hz * sCh + (long long)blockIdx.y * BM * ldc;

    const int t    = threadIdx.x;
    const int warp = t >> 5, lane = t & 31;
    const int g = lane >> 2, tg = lane & 3;
    const int m_base = (warp >> 1) * 32;          // 4 warps along M
    const int n_base = (warp & 1) * 32;           // 2 warps along N

    float c[2][4][4];
#pragma unroll
    for (int i = 0; i < 2; i++)
#pragma unroll
        for (int j = 0; j < 4; j++)
#pragma unroll
            for (int r = 0; r < 4; r++) c[i][j][r] = 0.f;

    for (int k0 = 0; k0 < K; k0 += BK) {
#pragma unroll
        for (int i = 0; i < 4; i++) {
            const int idx = i * 256 + t;
            const int r   = idx >> 3;
            const int c4  = (idx & 7) * 4;
            *(float4*)&As[r][c4] = *(const float4*)(Ab + (long long)r * lda + k0 + c4);
        }
#pragma unroll
        for (int i = 0; i < 2; i++) {
            const int idx = i * 256 + t;
            const int kr  = idx >> 4;
            const int n4  = (idx & 15) * 4;
            *(float4*)&Bs[kr][n4] = *(const float4*)(Bb + (long long)(k0 + kr) * ldb + n4);
        }
        __syncthreads();

#pragma unroll
        for (int kk = 0; kk < BK; kk += 8) {
            uint32_t af[2][4], bf[4][2];
#pragma unroll
            for (int mi = 0; mi < 2; mi++) {
                const int m = m_base + mi * 16;
                af[mi][0] = f2tf(As[m + g][kk + tg]);
                af[mi][1] = f2tf(As[m + 8 + g][kk + tg]);
                af[mi][2] = f2tf(As[m + g][kk + 4 + tg]);
                af[mi][3] = f2tf(As[m + 8 + g][kk + 4 + tg]);
            }
#pragma unroll
            for (int ni = 0; ni < 4; ni++) {
                const int n = n_base + ni * 8;
                bf[ni][0] = f2tf(Bs[kk + tg][n + g]);
                bf[ni][1] = f2tf(Bs[kk + 4 + tg][n + g]);
            }
#pragma unroll
            for (int mi = 0; mi < 2; mi++)
#pragma unroll
                for (int ni = 0; ni < 4; ni++)
                    mma_tf32(c[mi][ni], af[mi], bf[ni]);
        }
        __syncthreads();
    }

#pragma unroll
    for (int mi = 0; mi < 2; mi++) {
#pragma unroll
        for (int ni = 0; ni < 4; ni++) {
            const int row = m_base + mi * 16 + g;
            const int col = n_base + ni * 8 + tg * 2;
            *(float2*)(Cb + (long long)row * ldc + col) = make_float2(c[mi][ni][0], c[mi][ni][1]);
            *(float2*)(Cb + (long long)(row + 8) * ldc + col) = make_float2(c[mi][ni][2], c[mi][ni][3]);
        }
    }
}

// ---------------------------------------------------------------------------
// Row softmax over last axis (row length 2048), one block (256 threads) per row.
// ---------------------------------------------------------------------------
__global__ __launch_bounds__(256) void softmax_kernel(float* __restrict__ Wt)
{
    float* p = Wt + (long long)blockIdx.x * 2048;
    const int t = threadIdx.x;
    float4 x0 = ((const float4*)p)[t];
    float4 x1 = ((const float4*)p)[t + 256];

    float m = fmaxf(fmaxf(fmaxf(x0.x, x0.y), fmaxf(x0.z, x0.w)),
                    fmaxf(fmaxf(x1.x, x1.y), fmaxf(x1.z, x1.w)));
#pragma unroll
    for (int o = 16; o; o >>= 1) m = fmaxf(m, __shfl_xor_sync(0xffffffffu, m, o));

    __shared__ float redm[8], reds[8];
    if ((t & 31) == 0) redm[t >> 5] = m;
    __syncthreads();
    m = redm[0];
#pragma unroll
    for (int i = 1; i < 8; i++) m = fmaxf(m, redm[i]);

    x0.x = __expf(x0.x - m); x0.y = __expf(x0.y - m);
    x0.z = __expf(x0.z - m); x0.w = __expf(x0.w - m);
    x1.x = __expf(x1.x - m); x1.y = __expf(x1.y - m);
    x1.z = __expf(x1.z - m); x1.w = __expf(x1.w - m);

    float s = x0.x + x0.y + x0.z + x0.w + x1.x + x1.y + x1.z + x1.w;
#pragma unroll
    for (int o = 16; o; o >>= 1) s += __shfl_xor_sync(0xffffffffu, s, o);
    if ((t & 31) == 0) reds[t >> 5] = s;
    __syncthreads();
    s = reds[0] + reds[1] + reds[2] + reds[3] + reds[4] + reds[5] + reds[6] + reds[7];

    const float inv = 1.0f / s;
    x0.x *= inv; x0.y *= inv; x0.z *= inv; x0.w *= inv;
    x1.x *= inv; x1.y *= inv; x1.z *= inv; x1.w *= inv;
    ((float4*)p)[t]       = x0;
    ((float4*)p)[t + 256] = x1;
}

// ---------------------------------------------------------------------------
extern "C" void kernel_launch(void* const* d_in, const int* /*in_sizes*/, int /*n_in*/,
                              void* d_out, int out_size)
{
    const float* query = (const float*)d_in[0];
    const float* key_i = (const float*)d_in[1];
    const float* value = (const float*)d_in[2];
    const float* Wq    = (const float*)d_in[3];
    const float* Wk    = (const float*)d_in[4];
    const float* Wv    = (const float*)d_in[5];
    const float* Wo    = (const float*)d_in[6];
    float* out = (float*)d_out;

    float *q, *k, *v, *attn, *wbuf;
    cudaGetSymbolAddress((void**)&q,    g_q);
    cudaGetSymbolAddress((void**)&k,    g_k);
    cudaGetSymbolAddress((void**)&v,    g_v);
    cudaGetSymbolAddress((void**)&attn, g_attn);
    if ((long long)out_size >= OUT_ELEMS + W_ELEMS) {
        wbuf = out + OUT_ELEMS;                 // tuple-concat output: [out | weights]
    } else {
        cudaGetSymbolAddress((void**)&wbuf, g_weights);
    }

    const long long TD = (long long)Tc * Dc;
    const long long TT = (long long)Tc * Tc;

    // 1) Projections: y = x @ W^T   (M=4096, N=1024, K=1024)
    dim3 gp(Dc / 128, (Bc * Tc) / 128, 1);
    gemm_nt_tc<<<gp, 256>>>(query, Wq, q, Dc, Dc, Dc, Dc, 1, 0, 0, 0, 0, 0, 0, 1.f);
    gemm_nt_tc<<<gp, 256>>>(key_i, Wk, k, Dc, Dc, Dc, Dc, 1, 0, 0, 0, 0, 0, 0, 1.f);
    gemm_nt_tc<<<gp, 256>>>(value, Wv, v, Dc, Dc, Dc, Dc, 1, 0, 0, 0, 0, 0, 0, 1.f);

    // 2) Scores = (q_h @ k_h^T) / 8  per (b,h); weights layout [B,H,T,T]
    dim3 gs(Tc / 128, Tc / 128, Bc * Hc);
    gemm_nt_tc<<<gs, 256>>>(q, k, wbuf, DKc, Dc, Dc, Tc, Hc,
                            TD, DKc, TD, DKc,
                            (long long)Hc * TT, TT, 0.125f);

    // 3) Row softmax over 2048-length rows (B*H*T rows)
    softmax_kernel<<<Bc * Hc * Tc, 256>>>(wbuf);

    // 4) attn = weights @ v  per (b,h) -> packed back into [B,T,D]
    dim3 gv(1, Tc / 128, Bc * Hc);
    gemm_nn_tc<<<gv, 256>>>(wbuf, v, attn, Tc, Tc, Dc, Dc, Hc,
                            (long long)Hc * TT, TT,
                            TD, DKc, TD, DKc);

    // 5) out = attn @ Wo^T
    gemm_nt_tc<<<gp, 256>>>(attn, Wo, out, Dc, Dc, Dc, Dc, 1, 0, 0, 0, 0, 0, 0, 1.f);
}